// round 15
// baseline (speedup 1.0000x reference)
#include <cuda_runtime.h>
#include <cuda_bf16.h>
#include <cstdint>
#include <math.h>

// Problem constants
#define BATCH 4
#define SEQ   2048
#define HEADS 16
#define HDIM  64
#define DIN   1024
#define M_TOT (BATCH * SEQ)   // 8192
#define NBH   (BATCH * HEADS) // 64

// Int8 hi/lo operands for projection (t = 128*h + l, per-row scale)
__device__ int8_t g_xqh[M_TOT * DIN];
__device__ int8_t g_xql[M_TOT * DIN];
__device__ int8_t g_wqh[3 * DIN * DIN];   // W transposed: [z][n][k]
__device__ int8_t g_wql[3 * DIN * DIN];
__device__ float  g_sx[M_TOT];            // x row scales
__device__ float  g_sw[3 * DIN];          // W column scales
// bf16 hi/lo attention operands (R7 layout)
__device__ __nv_bfloat16 g_qh[NBH * SEQ * HDIM];   // [bh][s][d]
__device__ __nv_bfloat16 g_ql[NBH * SEQ * HDIM];
__device__ __nv_bfloat16 g_kh[NBH * SEQ * HDIM];   // [bh][t][d]
__device__ __nv_bfloat16 g_kl[NBH * SEQ * HDIM];
__device__ __nv_bfloat16 g_vth[NBH * HDIM * SEQ];  // [bh][d][t]
__device__ __nv_bfloat16 g_vtl[NBH * HDIM * SEQ];

// ---------------------------------------------------------------------------
// Helpers
// ---------------------------------------------------------------------------
__device__ __forceinline__ uint32_t smem_u32(const void* p) {
    uint32_t a;
    asm("{ .reg .u64 t; cvta.to.shared.u64 t, %1; cvt.u32.u64 %0, t; }"
        : "=r"(a) : "l"(p));
    return a;
}
__device__ __forceinline__ void cpa16(uint32_t dst, const void* src) {
    asm volatile("cp.async.cg.shared.global [%0], [%1], 16;"
                 :: "r"(dst), "l"(src) : "memory");
}
__device__ __forceinline__ void cpa_commit() {
    asm volatile("cp.async.commit_group;" ::: "memory");
}
__device__ __forceinline__ void cpa_wait0() {
    asm volatile("cp.async.wait_group 0;" ::: "memory");
}
// bf16 mma (attention)
__device__ __forceinline__ void mma16816(float* d, const uint32_t* a,
                                         const uint32_t* b) {
    asm volatile(
        "mma.sync.aligned.m16n8k16.row.col.f32.bf16.bf16.f32 "
        "{%0,%1,%2,%3}, {%4,%5,%6,%7}, {%8,%9}, {%0,%1,%2,%3};"
        : "+f"(d[0]), "+f"(d[1]), "+f"(d[2]), "+f"(d[3])
        : "r"(a[0]), "r"(a[1]), "r"(a[2]), "r"(a[3]), "r"(b[0]), "r"(b[1]));
}
// s8 mma k32 (projection)
__device__ __forceinline__ void mma16832s8(int* d, const uint32_t* a,
                                           const uint32_t* b) {
    asm volatile(
        "mma.sync.aligned.m16n8k32.row.col.s32.s8.s8.s32 "
        "{%0,%1,%2,%3}, {%4,%5,%6,%7}, {%8,%9}, {%0,%1,%2,%3};"
        : "+r"(d[0]), "+r"(d[1]), "+r"(d[2]), "+r"(d[3])
        : "r"(a[0]), "r"(a[1]), "r"(a[2]), "r"(a[3]), "r"(b[0]), "r"(b[1]));
}
__device__ __forceinline__ void ldsm4(uint32_t* r, uint32_t a) {
    asm volatile("ldmatrix.sync.aligned.m8n8.x4.shared.b16 {%0,%1,%2,%3}, [%4];"
                 : "=r"(r[0]), "=r"(r[1]), "=r"(r[2]), "=r"(r[3]) : "r"(a));
}
__device__ __forceinline__ uint32_t packbf2(float x, float y) {
    __nv_bfloat162 h = __floats2bfloat162_rn(x, y);
    return *(uint32_t*)&h;
}
__device__ __forceinline__ float ex2(float x) {
    float y;
    asm("ex2.approx.ftz.f32 %0, %1;" : "=f"(y) : "f"(x));
    return y;
}

// ---------------------------------------------------------------------------
// Quantization pre-passes
// ---------------------------------------------------------------------------
// x: one block per row. t = x * 16256/max; h = rint(t/128); l = rint(t-128h).
__global__ __launch_bounds__(128)
void quant_x_kernel(const float* __restrict__ x)
{
    __shared__ float red[4];
    const int row = blockIdx.x;
    const int tid = threadIdx.x;
    const float* xr = x + (size_t)row * DIN;
    float4 v0 = *(const float4*)&xr[tid * 8];
    float4 v1 = *(const float4*)&xr[tid * 8 + 4];
    float mx = fmaxf(fmaxf(fabsf(v0.x), fabsf(v0.y)),
                     fmaxf(fabsf(v0.z), fabsf(v0.w)));
    mx = fmaxf(mx, fmaxf(fmaxf(fabsf(v1.x), fabsf(v1.y)),
                         fmaxf(fabsf(v1.z), fabsf(v1.w))));
#pragma unroll
    for (int off = 16; off >= 1; off >>= 1)
        mx = fmaxf(mx, __shfl_xor_sync(0xffffffffu, mx, off));
    if ((tid & 31) == 0) red[tid >> 5] = mx;
    __syncthreads();
    mx = fmaxf(fmaxf(red[0], red[1]), fmaxf(red[2], red[3]));
    float s   = (mx > 0.0f) ? (mx / 16256.0f) : 1.0f;
    float inv = 16256.0f / fmaxf(mx, 1e-30f);
    if (mx == 0.0f) inv = 0.0f;
    if (tid == 0) g_sx[row] = s;

    float vv[8] = {v0.x, v0.y, v0.z, v0.w, v1.x, v1.y, v1.z, v1.w};
    char h8[8], l8[8];
#pragma unroll
    for (int e = 0; e < 8; e++) {
        float t = vv[e] * inv;
        float hf = rintf(t * 0.0078125f);      // /128
        float lf = rintf(t - 128.0f * hf);
        h8[e] = (char)(int)hf;
        l8[e] = (char)(int)lf;
    }
    *(uint2*)&g_xqh[(size_t)row * DIN + tid * 8] = *(uint2*)h8;
    *(uint2*)&g_xql[(size_t)row * DIN + tid * 8] = *(uint2*)l8;
}

// W: one block per (n, z) output column; emits W^T[n][k] int8 hi/lo + scale.
__global__ __launch_bounds__(128)
void quant_w_kernel(const float* __restrict__ Wq,
                    const float* __restrict__ Wk,
                    const float* __restrict__ Wv)
{
    __shared__ float red[4];
    const int n = blockIdx.x;
    const int z = blockIdx.y;
    const int tid = threadIdx.x;
    const float* W = (z == 0) ? Wq : ((z == 1) ? Wk : Wv);
    float v[8];
    float mx = 0.0f;
#pragma unroll
    for (int e = 0; e < 8; e++) {
        v[e] = W[(size_t)(tid * 8 + e) * DIN + n];
        mx = fmaxf(mx, fabsf(v[e]));
    }
#pragma unroll
    for (int off = 16; off >= 1; off >>= 1)
        mx = fmaxf(mx, __shfl_xor_sync(0xffffffffu, mx, off));
    if ((tid & 31) == 0) red[tid >> 5] = mx;
    __syncthreads();
    mx = fmaxf(fmaxf(red[0], red[1]), fmaxf(red[2], red[3]));
    float s   = (mx > 0.0f) ? (mx / 16256.0f) : 1.0f;
    float inv = 16256.0f / fmaxf(mx, 1e-30f);
    if (mx == 0.0f) inv = 0.0f;
    if (tid == 0) g_sw[z * DIN + n] = s;

    char h8[8], l8[8];
#pragma unroll
    for (int e = 0; e < 8; e++) {
        float t = v[e] * inv;
        float hf = rintf(t * 0.0078125f);
        float lf = rintf(t - 128.0f * hf);
        h8[e] = (char)(int)hf;
        l8[e] = (char)(int)lf;
    }
    size_t base = (size_t)z * DIN * DIN + (size_t)n * DIN + tid * 8;
    *(uint2*)&g_wqh[base] = *(uint2*)h8;
    *(uint2*)&g_wql[base] = *(uint2*)l8;
}

// ---------------------------------------------------------------------------
// Projection GEMM via s8 mma.m16n8k32 (2-term: 16384*h@h + 128*(h@l + l@h)).
// CTA tile 128(m) x 64(n), 256 threads, 8 warps (4m x 2n), warp 32x32, BK=32,
// double-buffered, 2 CTAs/SM. Row stride 48B (32B data + 16B pad) — the
// R12-verified conflict-free, 16B-aligned ldmatrix layout.
// z=0,1: A=x(m), B=W^T(n) -> Q,K.  z=2: A=W^T, B=x -> V^T (coalesced).
// ---------------------------------------------------------------------------
#define PROWB    48
#define QA_TILE  (128 * PROWB)         // 6144
#define QB_TILE  (64 * PROWB)          // 3072
#define AH_OFF   0
#define AL_OFF   QA_TILE               // 6144
#define BH_OFF   (2 * QA_TILE)         // 12288
#define BL_OFF   (2 * QA_TILE + QB_TILE) // 15360
#define PSTAGE_B (2 * QA_TILE + 2 * QB_TILE) // 18432
#define PSMEM    (2 * PSTAGE_B + 1536) // 38400

__device__ __forceinline__ void proj_load_chunk(
    uint32_t bufb,
    const int8_t* __restrict__ Ahp, const int8_t* __restrict__ Alp,
    const int8_t* __restrict__ Bhp, const int8_t* __restrict__ Blp,
    int arow0, int brow0, int k0, int tid)
{
    int row  = tid >> 1;                // 0..127
    int half = tid & 1;
    uint32_t so = (uint32_t)(row * PROWB + half * 16);
    int gofs = k0 + half * 16;          // 16 int8 per cpa16
    cpa16(bufb + AH_OFF + so, Ahp + (size_t)(arow0 + row) * DIN + gofs);
    cpa16(bufb + AL_OFF + so, Alp + (size_t)(arow0 + row) * DIN + gofs);
    if (tid < 128) {                    // B: 64 rows
        cpa16(bufb + BH_OFF + so, Bhp + (size_t)(brow0 + row) * DIN + gofs);
        cpa16(bufb + BL_OFF + so, Blp + (size_t)(brow0 + row) * DIN + gofs);
    }
}

__global__ __launch_bounds__(256, 2)
void proj_mma_kernel(const float* __restrict__ bq,
                     const float* __restrict__ bk,
                     const float* __restrict__ bv)
{
    extern __shared__ char sm[];
    const uint32_t sb = smem_u32(sm);
    const int tid = threadIdx.x;
    const int wid = tid >> 5;
    const int lane = tid & 31;
    const int grp = lane >> 2;
    const int tg  = lane & 3;
    const int wm  = wid >> 1;               // 0..3 -> m offset 32*wm
    const int wn  = wid & 1;                // 0..1 -> n offset 32*wn

    const int z = blockIdx.z;
    const float* bias = (z == 0) ? bq : ((z == 1) ? bk : bv);
    const int8_t* wh = g_wqh + (size_t)z * DIN * DIN;
    const int8_t* wl = g_wql + (size_t)z * DIN * DIN;
    __nv_bfloat16* outh = (z == 0) ? g_qh : ((z == 1) ? g_kh : g_vth);
    __nv_bfloat16* outl = (z == 0) ? g_ql : ((z == 1) ? g_kl : g_vtl);

    // Tile origins. z<2: A=x(128 rows), B=W^T(64 rows), grid (16,64).
    // z=2: A=W^T(128 rows, 8 tiles), B=x(64 rows, 128 tiles) via remap.
    const int8_t *Ahp, *Alp, *Bhp, *Blp;
    int arow0, brow0, m0 = 0, n0 = 0;
    if (z < 2) {
        m0 = blockIdx.y * 128; n0 = blockIdx.x * 64;
        Ahp = g_xqh; Alp = g_xql; arow0 = m0;
        Bhp = wh;    Blp = wl;    brow0 = n0;
    } else {
        int id = blockIdx.y * 16 + blockIdx.x;  // 0..1023
        Ahp = wh;    Alp = wl;    arow0 = (id >> 7) * 128;
        Bhp = g_xqh; Blp = g_xql; brow0 = (id & 127) * 64;
    }

    float* sSA   = (float*)(sm + 2 * PSTAGE_B);          // 128 A-row scales
    float* sSB   = (float*)(sm + 2 * PSTAGE_B + 512);    // 64 B-row scales
    float* sBias = (float*)(sm + 2 * PSTAGE_B + 768);    // up to 128
    if (z < 2) {
        if (tid < 128) sSA[tid] = g_sx[arow0 + tid];
        if (tid < 64)  sSB[tid] = g_sw[z * DIN + brow0 + tid];
        if (tid < 64)  sBias[tid] = bias[brow0 + tid];
    } else {
        if (tid < 128) sSA[tid] = g_sw[2 * DIN + arow0 + tid];
        if (tid < 64)  sSB[tid] = g_sx[brow0 + tid];
        if (tid < 128) sBias[tid] = bias[arow0 + tid];
    }

    const uint32_t a_off = (uint32_t)((((lane >> 3) & 1) * 8 + (lane & 7)) * PROWB +
                                      (lane >> 4) * 16);
    const uint32_t b_off = (uint32_t)(((((lane >> 4) << 3) | (lane & 7)) * PROWB) +
                                      ((lane >> 3) & 1) * 16);

    int d1[2][4][4], d2[2][4][4];
#pragma unroll
    for (int mi = 0; mi < 2; mi++)
#pragma unroll
        for (int ni = 0; ni < 4; ni++)
#pragma unroll
            for (int j = 0; j < 4; j++) { d1[mi][ni][j] = 0; d2[mi][ni][j] = 0; }

    proj_load_chunk(sb, Ahp, Alp, Bhp, Blp, arow0, brow0, 0, tid);
    cpa_commit();
    cpa_wait0();
    __syncthreads();

    const int NCHUNK = DIN / 32;            // 32
    for (int c = 0; c < NCHUNK; c++) {
        if (c + 1 < NCHUNK) {
            proj_load_chunk(sb + ((c + 1) & 1) * PSTAGE_B, Ahp, Alp, Bhp, Blp,
                            arow0, brow0, (c + 1) * 32, tid);
            cpa_commit();
        }
        const uint32_t bufb = sb + (c & 1) * PSTAGE_B;

        uint32_t ah[2][4], al[2][4];
#pragma unroll
        for (int mi = 0; mi < 2; mi++) {
            uint32_t ab = bufb + (uint32_t)((wm * 32 + mi * 16) * PROWB) + a_off;
            ldsm4(ah[mi], ab + AH_OFF);
            ldsm4(al[mi], ab + AL_OFF);
        }
#pragma unroll
        for (int np = 0; np < 2; np++) {
            uint32_t bh[4], bl[4];
            uint32_t bb = bufb + (uint32_t)((wn * 32 + np * 16) * PROWB) + b_off;
            ldsm4(bh, bb + BH_OFF);
            ldsm4(bl, bb + BL_OFF);
#pragma unroll
            for (int mi = 0; mi < 2; mi++) {
                mma16832s8(d1[mi][2 * np],     ah[mi], bh);
                mma16832s8(d1[mi][2 * np + 1], ah[mi], bh + 2);
                mma16832s8(d2[mi][2 * np],     ah[mi], bl);
                mma16832s8(d2[mi][2 * np],     al[mi], bh);
                mma16832s8(d2[mi][2 * np + 1], ah[mi], bl + 2);
                mma16832s8(d2[mi][2 * np + 1], al[mi], bh + 2);
            }
        }
        cpa_wait0();
        __syncthreads();
    }

    // Epilogue: dequant, bias, bf16 hi/lo split, scatter (R7 patterns)
    if (z < 2) {
#pragma unroll
        for (int mi = 0; mi < 2; mi++) {
#pragma unroll
            for (int ni = 0; ni < 4; ni++) {
                int ncol = wn * 32 + ni * 8 + tg * 2;
                int n = n0 + ncol;
                int h = n >> 6;
                int dd = n & 63;
                float sn0 = sSB[ncol], sn1 = sSB[ncol + 1];
                float b0 = sBias[ncol], b1 = sBias[ncol + 1];
#pragma unroll
                for (int rr = 0; rr < 2; rr++) {
                    int rowoff = wm * 32 + mi * 16 + grp + rr * 8;
                    int m = m0 + rowoff;
                    float sm_ = sSA[rowoff];
                    int bb = m >> 11;
                    int s  = m & 2047;
                    float vx = sm_ * sn0 * (16384.0f * (float)d1[mi][ni][rr * 2 + 0]
                                            + 128.0f * (float)d2[mi][ni][rr * 2 + 0]) + b0;
                    float vy = sm_ * sn1 * (16384.0f * (float)d1[mi][ni][rr * 2 + 1]
                                            + 128.0f * (float)d2[mi][ni][rr * 2 + 1]) + b1;
                    __nv_bfloat16 hx = __float2bfloat16(vx);
                    __nv_bfloat16 hy = __float2bfloat16(vy);
                    __nv_bfloat16 lx = __float2bfloat16(vx - __bfloat162float(hx));
                    __nv_bfloat16 ly = __float2bfloat16(vy - __bfloat162float(hy));
                    size_t a = ((size_t)(bb * HEADS + h) * SEQ + s) * HDIM + dd;
                    *(__nv_bfloat162*)&outh[a] = __halves2bfloat162(hx, hy);
                    *(__nv_bfloat162*)&outl[a] = __halves2bfloat162(lx, ly);
                }
            }
        }
    } else {
        // D'[i = W-col][j = x-row] -> V^T[bh][d][t]
#pragma unroll
        for (int mi = 0; mi < 2; mi++) {
#pragma unroll
            for (int rr = 0; rr < 2; rr++) {
                int rowoff = wm * 32 + mi * 16 + grp + rr * 8;
                int i = arow0 + rowoff;
                int h  = i >> 6;
                int dd = i & 63;
                float si = sSA[rowoff];
                float bi = sBias[rowoff];
#pragma unroll
                for (int ni = 0; ni < 4; ni++) {
                    int jcol = wn * 32 + ni * 8 + tg * 2;
                    int j = brow0 + jcol;
                    float sj0 = sSB[jcol], sj1 = sSB[jcol + 1];
                    int bb = j >> 11;
                    int t  = j & 2047;
                    float vx = si * sj0 * (16384.0f * (float)d1[mi][ni][rr * 2 + 0]
                                           + 128.0f * (float)d2[mi][ni][rr * 2 + 0]) + bi;
                    float vy = si * sj1 * (16384.0f * (float)d1[mi][ni][rr * 2 + 1]
                                           + 128.0f * (float)d2[mi][ni][rr * 2 + 1]) + bi;
                    __nv_bfloat16 hx = __float2bfloat16(vx);
                    __nv_bfloat16 hy = __float2bfloat16(vy);
                    __nv_bfloat16 lx = __float2bfloat16(vx - __bfloat162float(hx));
                    __nv_bfloat16 ly = __float2bfloat16(vy - __bfloat162float(hy));
                    size_t a = ((size_t)(bb * HEADS + h) * HDIM + dd) * SEQ + t;
                    *(__nv_bfloat162*)&outh[a] = __halves2bfloat162(hx, hy);
                    *(__nv_bfloat162*)&outl[a] = __halves2bfloat162(lx, ly);
                }
            }
        }
    }
}

// ---------------------------------------------------------------------------
// Flash attention — EXACT R7 (best measured, ~496us). bf16 3-term,
// 128-thread CTAs (4 warps x 16 q-rows), fixed-max softmax.
// ---------------------------------------------------------------------------
#define ASTR    72
#define KTILE_B (64 * ASTR * 2)      // 9216
#define KH_OFF2 0
#define KL_OFF2 KTILE_B
#define VH_OFF2 (2 * KTILE_B)
#define VL_OFF2 (3 * KTILE_B)
#define ABUF_B  (4 * KTILE_B)        // 36864
#define ASMEM   (2 * ABUF_B)         // 73728
#define EXSC    0.18033688011112042f // 0.125 * log2(e)

__device__ __forceinline__ void attn_load(
    uint32_t bufb,
    const __nv_bfloat16* __restrict__ kh, const __nv_bfloat16* __restrict__ kl,
    const __nv_bfloat16* __restrict__ vth, const __nv_bfloat16* __restrict__ vtl,
    int t0, int tid)
{
#pragma unroll
    for (int i = 0; i < 4; i++) {
        int idx = tid + i * 128;
        int row = idx >> 3;
        int c8  = (idx & 7) * 8;
        uint32_t so = (uint32_t)(row * ASTR + c8) * 2;
        cpa16(bufb + KH_OFF2 + so, kh  + (size_t)(t0 + row) * HDIM + c8);
        cpa16(bufb + KL_OFF2 + so, kl  + (size_t)(t0 + row) * HDIM + c8);
        cpa16(bufb + VH_OFF2 + so, vth + (size_t)row * SEQ + t0 + c8);
        cpa16(bufb + VL_OFF2 + so, vtl + (size_t)row * SEQ + t0 + c8);
    }
}

__global__ __launch_bounds__(128, 3)
void attn_mma_kernel(float* __restrict__ out)
{
    extern __shared__ char sm[];
    const uint32_t sb = smem_u32(sm);
    const int tid  = threadIdx.x;
    const int wid  = tid >> 5;
    const int lane = tid & 31;
    const int grp  = lane >> 2;
    const int tg   = lane & 3;

    const int bh = blockIdx.y;
    const int m0 = blockIdx.x * 64;

    const uint32_t lm_off = (uint32_t)(((((lane >> 4) << 3) | (lane & 7)) * 144) +
                                       ((lane >> 3) & 1) * 16);

    const __nv_bfloat16* kh  = g_kh  + (size_t)bh * SEQ * HDIM;
    const __nv_bfloat16* kl  = g_kl  + (size_t)bh * SEQ * HDIM;
    const __nv_bfloat16* vth = g_vth + (size_t)bh * HDIM * SEQ;
    const __nv_bfloat16* vtl = g_vtl + (size_t)bh * HDIM * SEQ;
    const uint32_t* Qh32 = (const uint32_t*)(g_qh + (size_t)bh * SEQ * HDIM);
    const uint32_t* Ql32 = (const uint32_t*)(g_ql + (size_t)bh * SEQ * HDIM);

    attn_load(sb, kh, kl, vth, vtl, 0, tid);
    cpa_commit();

    uint32_t ah[4][4], al[4][4];
    {
        int r0 = m0 + wid * 16 + grp;
#pragma unroll
        for (int kk = 0; kk < 4; kk++) {
            int b0 = r0 * 32 + kk * 8 + tg;
            ah[kk][0] = Qh32[b0];
            ah[kk][1] = Qh32[b0 + 8 * 32];
            ah[kk][2] = Qh32[b0 + 4];
            ah[kk][3] = Qh32[b0 + 8 * 32 + 4];
            al[kk][0] = Ql32[b0];
            al[kk][1] = Ql32[b0 + 8 * 32];
            al[kk][2] = Ql32[b0 + 4];
            al[kk][3] = Ql32[b0 + 8 * 32 + 4];
        }
    }

    float o[8][4];
    float lacc0 = 0.0f, lacc1 = 0.0f;
#pragma unroll
    for (int j = 0; j < 8; j++)
#pragma unroll
        for (int q = 0; q < 4; q++) o[j][q] = 0.0f;

    cpa_wait0();
    __syncthreads();

    for (int t0 = 0; t0 < SEQ; t0 += 64) {
        const int c = t0 >> 6;
        if (t0 + 64 < SEQ) {
            attn_load(sb + ((c + 1) & 1) * ABUF_B, kh, kl, vth, vtl, t0 + 64, tid);
            cpa_commit();
        }
        const uint32_t bufb = sb + (c & 1) * ABUF_B;
        const uint32_t khb = bufb + KH_OFF2 + lm_off;
        const uint32_t klb = bufb + KL_OFF2 + lm_off;
        const uint32_t vhb = bufb + VH_OFF2 + lm_off;
        const uint32_t vlb = bufb + VL_OFF2 + lm_off;

        float s[8][4];
#pragma unroll
        for (int j = 0; j < 8; j++)
#pragma unroll
            for (int q = 0; q < 4; q++) s[j][q] = 0.0f;

#pragma unroll
        for (int kk = 0; kk < 4; kk++) {
#pragma unroll
            for (int jp = 0; jp < 4; jp++) {
                uint32_t kbh[4], kbl[4];
                ldsm4(kbh, khb + jp * 2304 + kk * 32);
                ldsm4(kbl, klb + jp * 2304 + kk * 32);
                mma16816(s[2 * jp],     ah[kk], kbh);
                mma16816(s[2 * jp],     ah[kk], kbl);
                mma16816(s[2 * jp],     al[kk], kbh);
                mma16816(s[2 * jp + 1], ah[kk], kbh + 2);
                mma16816(s[2 * jp + 1], ah[kk], kbl + 2);
                mma16816(s[2 * jp + 1], al[kk], kbh + 2);
            }
        }

#pragma unroll
        for (int kt = 0; kt < 4; kt++) {
            const int j0 = 2 * kt, j1 = 2 * kt + 1;
            float p00 = ex2(s[j0][0] * EXSC), p01 = ex2(s[j0][1] * EXSC);
            float p02 = ex2(s[j0][2] * EXSC), p03 = ex2(s[j0][3] * EXSC);
            float p10 = ex2(s[j1][0] * EXSC), p11 = ex2(s[j1][1] * EXSC);
            float p12 = ex2(s[j1][2] * EXSC), p13 = ex2(s[j1][3] * EXSC);
            lacc0 += p00 + p01 + p10 + p11;
            lacc1 += p02 + p03 + p12 + p13;

            uint32_t pah[4], pal[4];
            pah[0] = packbf2(p00, p01);
            pah[1] = packbf2(p02, p03);
            pah[2] = packbf2(p10, p11);
            pah[3] = packbf2(p12, p13);
            __nv_bfloat162 h;
            h = *(__nv_bfloat162*)&pah[0];
            pal[0] = packbf2(p00 - __bfloat162float(h.x), p01 - __bfloat162float(h.y));
            h = *(__nv_bfloat162*)&pah[1];
            pal[1] = packbf2(p02 - __bfloat162float(h.x), p03 - __bfloat162float(h.y));
            h = *(__nv_bfloat162*)&pah[2];
            pal[2] = packbf2(p10 - __bfloat162float(h.x), p11 - __bfloat162float(h.y));
            h = *(__nv_bfloat162*)&pah[3];
            pal[3] = packbf2(p12 - __bfloat162float(h.x), p13 - __bfloat162float(h.y));

#pragma unroll
            for (int jp = 0; jp < 4; jp++) {
                uint32_t vbh[4], vbl[4];
                ldsm4(vbh, vhb + jp * 2304 + kt * 32);
                ldsm4(vbl, vlb + jp * 2304 + kt * 32);
                mma16816(o[2 * jp],     pah, vbh);
                mma16816(o[2 * jp],     pah, vbl);
                mma16816(o[2 * jp],     pal, vbh);
                mma16816(o[2 * jp + 1], pah, vbh + 2);
                mma16816(o[2 * jp + 1], pah, vbl + 2);
                mma16816(o[2 * jp + 1], pal, vbh + 2);
            }
        }

        cpa_wait0();
        __syncthreads();
    }

    lacc0 += __shfl_xor_sync(0xffffffffu, lacc0, 1);
    lacc0 += __shfl_xor_sync(0xffffffffu, lacc0, 2);
    lacc1 += __shfl_xor_sync(0xffffffffu, lacc1, 1);
    lacc1 += __shfl_xor_sync(0xffffffffu, lacc1, 2);

    const int b = bh >> 4;
    const int h = bh & 15;
    const float inv0 = 1.0f / lacc0;
    const float inv1 = 1.0f / lacc1;
    const int s0 = m0 + wid * 16 + grp;
#pragma unroll
    for (int jd = 0; jd < 8; jd++) {
        int dd = jd * 8 + tg * 2;
        float2 v0 = make_float2(o[jd][0] * inv0, o[jd][1] * inv0);
        float2 v1 = make_float2(o[jd][2] * inv1, o[jd][3] * inv1);
        *(float2*)&out[((size_t)(b * SEQ + s0)) * (HEADS * HDIM) + h * HDIM + dd] = v0;
        *(float2*)&out[((size_t)(b * SEQ + s0 + 8)) * (HEADS * HDIM) + h * HDIM + dd] = v1;
    }
}

// ---------------------------------------------------------------------------
extern "C" void kernel_launch(void* const* d_in, const int* in_sizes, int n_in,
                              void* d_out, int out_size)
{
    const float* x  = (const float*)d_in[0];
    const float* Wq = (const float*)d_in[1];
    const float* bq = (const float*)d_in[2];
    const float* Wk = (const float*)d_in[3];
    const float* bk = (const float*)d_in[4];
    const float* Wv = (const float*)d_in[5];
    const float* bv = (const float*)d_in[6];
    float* out = (float*)d_out;

    cudaFuncSetAttribute(proj_mma_kernel,
                         cudaFuncAttributeMaxDynamicSharedMemorySize, PSMEM);
    cudaFuncSetAttribute(attn_mma_kernel,
                         cudaFuncAttributeMaxDynamicSharedMemorySize, ASMEM);

    quant_x_kernel<<<M_TOT, 128>>>(x);
    quant_w_kernel<<<dim3(DIN, 3), 128>>>(Wq, Wk, Wv);
    proj_mma_kernel<<<dim3(16, 64, 3), 256, PSMEM>>>(bq, bk, bv);

    dim3 g2(SEQ / 64, NBH);
    attn_mma_kernel<<<g2, 128, ASMEM>>>(out);
}

// round 16
// speedup vs baseline: 1.7147x; 1.7147x over previous
#include <cuda_runtime.h>
#include <cuda_bf16.h>
#include <cstdint>
#include <math.h>

// Problem constants
#define BATCH 4
#define SEQ   2048
#define HEADS 16
#define HDIM  64
#define DIN   1024
#define M_TOT (BATCH * SEQ)   // 8192
#define NBH   (BATCH * HEADS) // 64

// Scratch: bf16 hi/lo operands
__device__ __nv_bfloat16 g_xh[M_TOT * DIN];
__device__ __nv_bfloat16 g_xl[M_TOT * DIN];
__device__ __nv_bfloat16 g_wh[3 * DIN * DIN];   // W transposed: [z][n][k]
__device__ __nv_bfloat16 g_wl[3 * DIN * DIN];
__device__ __nv_bfloat16 g_qh[NBH * SEQ * HDIM];   // [bh][s][d]
__device__ __nv_bfloat16 g_ql[NBH * SEQ * HDIM];
__device__ __nv_bfloat16 g_kh[NBH * SEQ * HDIM];   // [bh][t][d]
__device__ __nv_bfloat16 g_kl[NBH * SEQ * HDIM];
__device__ __nv_bfloat16 g_vth[NBH * HDIM * SEQ];  // [bh][d][t]  (transposed)
__device__ __nv_bfloat16 g_vtl[NBH * HDIM * SEQ];

// ---------------------------------------------------------------------------
// Helpers
// ---------------------------------------------------------------------------
__device__ __forceinline__ uint32_t smem_u32(const void* p) {
    uint32_t a;
    asm("{ .reg .u64 t; cvta.to.shared.u64 t, %1; cvt.u32.u64 %0, t; }"
        : "=r"(a) : "l"(p));
    return a;
}
__device__ __forceinline__ void cpa16(uint32_t dst, const void* src) {
    asm volatile("cp.async.cg.shared.global [%0], [%1], 16;"
                 :: "r"(dst), "l"(src) : "memory");
}
__device__ __forceinline__ void cpa_commit() {
    asm volatile("cp.async.commit_group;" ::: "memory");
}
__device__ __forceinline__ void cpa_wait0() {
    asm volatile("cp.async.wait_group 0;" ::: "memory");
}
__device__ __forceinline__ void mma16816(float* d, const uint32_t* a,
                                         const uint32_t* b) {
    asm volatile(
        "mma.sync.aligned.m16n8k16.row.col.f32.bf16.bf16.f32 "
        "{%0,%1,%2,%3}, {%4,%5,%6,%7}, {%8,%9}, {%0,%1,%2,%3};"
        : "+f"(d[0]), "+f"(d[1]), "+f"(d[2]), "+f"(d[3])
        : "r"(a[0]), "r"(a[1]), "r"(a[2]), "r"(a[3]), "r"(b[0]), "r"(b[1]));
}
__device__ __forceinline__ void ldsm4(uint32_t* r, uint32_t a) {
    asm volatile("ldmatrix.sync.aligned.m8n8.x4.shared.b16 {%0,%1,%2,%3}, [%4];"
                 : "=r"(r[0]), "=r"(r[1]), "=r"(r[2]), "=r"(r[3]) : "r"(a));
}
__device__ __forceinline__ uint32_t packbf2(float x, float y) {
    __nv_bfloat162 h = __floats2bfloat162_rn(x, y);
    return *(uint32_t*)&h;
}
__device__ __forceinline__ float ex2(float x) {
    float y;
    asm("ex2.approx.ftz.f32 %0, %1;" : "=f"(y) : "f"(x));
    return y;
}

// ---------------------------------------------------------------------------
// Merged pre-pass: fp32 -> bf16 hi/lo split of x AND transposed W (one launch)
// blocks [0, 8192): x-convert; blocks [8192, 11264): W transpose+convert.
// ---------------------------------------------------------------------------
__global__ __launch_bounds__(256)
void convert_all_kernel(const float* __restrict__ x,
                        const float* __restrict__ Wq,
                        const float* __restrict__ Wk,
                        const float* __restrict__ Wv)
{
    __shared__ float t[32][33];
    if (blockIdx.x < 8192) {
        int i = blockIdx.x * 256 + threadIdx.x;     // float4 index
        float4 v = ((const float4*)x)[i];
        __nv_bfloat16 h0 = __float2bfloat16(v.x);
        __nv_bfloat16 h1 = __float2bfloat16(v.y);
        __nv_bfloat16 h2 = __float2bfloat16(v.z);
        __nv_bfloat16 h3 = __float2bfloat16(v.w);
        __nv_bfloat16 l0 = __float2bfloat16(v.x - __bfloat162float(h0));
        __nv_bfloat16 l1 = __float2bfloat16(v.y - __bfloat162float(h1));
        __nv_bfloat16 l2 = __float2bfloat16(v.z - __bfloat162float(h2));
        __nv_bfloat16 l3 = __float2bfloat16(v.w - __bfloat162float(h3));
        __nv_bfloat162* ph = (__nv_bfloat162*)g_xh;
        __nv_bfloat162* pl = (__nv_bfloat162*)g_xl;
        ph[2 * i]     = __halves2bfloat162(h0, h1);
        ph[2 * i + 1] = __halves2bfloat162(h2, h3);
        pl[2 * i]     = __halves2bfloat162(l0, l1);
        pl[2 * i + 1] = __halves2bfloat162(l2, l3);
    } else {
        int wb  = blockIdx.x - 8192;                // 0..3071
        int z   = wb >> 10;                          // /1024
        int rem = wb & 1023;
        int n0 = (rem & 31) * 32;
        int k0 = (rem >> 5) * 32;
        const float* W = (z == 0) ? Wq : ((z == 1) ? Wk : Wv);
        __nv_bfloat16* oh = g_wh + (size_t)z * DIN * DIN;
        __nv_bfloat16* ol = g_wl + (size_t)z * DIN * DIN;
        int tx = threadIdx.x & 31, ty = threadIdx.x >> 5;
#pragma unroll
        for (int r = 0; r < 4; r++)
            t[ty + r * 8][tx] = W[(size_t)(k0 + ty + r * 8) * DIN + n0 + tx];
        __syncthreads();
#pragma unroll
        for (int r = 0; r < 4; r++) {
            int n = ty + r * 8;
            float v = t[tx][n];
            __nv_bfloat16 h = __float2bfloat16(v);
            __nv_bfloat16 l = __float2bfloat16(v - __bfloat162float(h));
            oh[(size_t)(n0 + n) * DIN + k0 + tx] = h;
            ol[(size_t)(n0 + n) * DIN + k0 + tx] = l;
        }
    }
}

// ---------------------------------------------------------------------------
// Projection GEMM via mma.sync + ldmatrix (R7 — best measured).
// z=0,1: D[m=x-rows][n=W-cols]  -> Q,K in [bh][s][d]
// z=2  : SWAPPED  D'[i=W-cols][j=x-rows] -> V^T in [bh][d][t], coalesced stores
// ---------------------------------------------------------------------------
#define PSTR     40
#define PTILE_B  (128 * PSTR * 2)
#define PBUF_B   (4 * PTILE_B)
#define AH_OFF   0
#define AL_OFF   PTILE_B
#define BH_OFF   (2 * PTILE_B)
#define BL_OFF   (3 * PTILE_B)
#define PSMEM    (2 * PBUF_B + 512)

__device__ __forceinline__ void proj_load_chunk(
    uint32_t bufb,
    const __nv_bfloat16* __restrict__ Ahp, const __nv_bfloat16* __restrict__ Alp,
    const __nv_bfloat16* __restrict__ Bhp, const __nv_bfloat16* __restrict__ Blp,
    int arow0, int brow0, int k0, int tid)
{
#pragma unroll
    for (int i = 0; i < 2; i++) {
        int idx = tid + i * 256;
        int row = idx >> 2;
        int c8  = (idx & 3) * 8;
        uint32_t so = (uint32_t)(row * PSTR + c8) * 2;
        cpa16(bufb + AH_OFF + so, Ahp + (size_t)(arow0 + row) * DIN + k0 + c8);
        cpa16(bufb + AL_OFF + so, Alp + (size_t)(arow0 + row) * DIN + k0 + c8);
        cpa16(bufb + BH_OFF + so, Bhp + (size_t)(brow0 + row) * DIN + k0 + c8);
        cpa16(bufb + BL_OFF + so, Blp + (size_t)(brow0 + row) * DIN + k0 + c8);
    }
}

__global__ __launch_bounds__(256, 2)
void proj_mma_kernel(const float* __restrict__ bq,
                     const float* __restrict__ bk,
                     const float* __restrict__ bv)
{
    extern __shared__ char sm[];
    const uint32_t sb = smem_u32(sm);
    const int tid = threadIdx.x;
    const int wid = tid >> 5;
    const int lane = tid & 31;
    const int grp = lane >> 2;
    const int tg  = lane & 3;
    const int wm  = wid >> 1;
    const int wn  = wid & 1;

    const int z  = blockIdx.z;
    const int n0 = blockIdx.x * 128;
    const int m0 = blockIdx.y * 128;

    const float* bias = (z == 0) ? bq : ((z == 1) ? bk : bv);
    const __nv_bfloat16* wh = g_wh + (size_t)z * DIN * DIN;
    const __nv_bfloat16* wl = g_wl + (size_t)z * DIN * DIN;
    __nv_bfloat16* outh = (z == 0) ? g_qh : ((z == 1) ? g_kh : g_vth);
    __nv_bfloat16* outl = (z == 0) ? g_ql : ((z == 1) ? g_kl : g_vtl);

    const __nv_bfloat16 *Ahp, *Alp, *Bhp, *Blp;
    int arow0, brow0;
    if (z < 2) { Ahp = g_xh; Alp = g_xl; arow0 = m0; Bhp = wh; Blp = wl; brow0 = n0; }
    else       { Ahp = wh;   Alp = wl;   arow0 = n0; Bhp = g_xh; Blp = g_xl; brow0 = m0; }

    float* sBias = (float*)(sm + 2 * PBUF_B);
    if (tid < 128) sBias[tid] = bias[((z < 2) ? brow0 : arow0) + tid];

    const uint32_t a_off = (uint32_t)((((lane >> 3) & 1) * 8 + (lane & 7)) * 80 +
                                      (lane >> 4) * 16);
    const uint32_t b_off = (uint32_t)(((((lane >> 4) << 3) | (lane & 7)) * 80) +
                                      ((lane >> 3) & 1) * 16);

    float d[2][8][4];
#pragma unroll
    for (int mi = 0; mi < 2; mi++)
#pragma unroll
        for (int ni = 0; ni < 8; ni++)
#pragma unroll
            for (int j = 0; j < 4; j++) d[mi][ni][j] = 0.0f;

    proj_load_chunk(sb, Ahp, Alp, Bhp, Blp, arow0, brow0, 0, tid);
    cpa_commit();
    cpa_wait0();
    __syncthreads();

    const int NCHUNK = DIN / 32;
    for (int c = 0; c < NCHUNK; c++) {
        if (c + 1 < NCHUNK) {
            proj_load_chunk(sb + ((c + 1) & 1) * PBUF_B, Ahp, Alp, Bhp, Blp,
                            arow0, brow0, (c + 1) * 32, tid);
            cpa_commit();
        }
        const uint32_t bufb = sb + (c & 1) * PBUF_B;

#pragma unroll
        for (int ks = 0; ks < 2; ks++) {
            uint32_t ah[2][4], al[2][4];
#pragma unroll
            for (int mi = 0; mi < 2; mi++) {
                uint32_t ab = bufb + (uint32_t)((wm * 32 + mi * 16) * 80 + ks * 32) + a_off;
                ldsm4(ah[mi], ab + AH_OFF);
                ldsm4(al[mi], ab + AL_OFF);
            }
#pragma unroll
            for (int np = 0; np < 4; np++) {
                uint32_t bh[4], bl[4];
                uint32_t bb = bufb + (uint32_t)((wn * 64 + np * 16) * 80 + ks * 32) + b_off;
                ldsm4(bh, bb + BH_OFF);
                ldsm4(bl, bb + BL_OFF);
#pragma unroll
                for (int mi = 0; mi < 2; mi++) {
                    mma16816(d[mi][2 * np],     ah[mi], bh);
                    mma16816(d[mi][2 * np],     ah[mi], bl);
                    mma16816(d[mi][2 * np],     al[mi], bh);
                    mma16816(d[mi][2 * np + 1], ah[mi], bh + 2);
                    mma16816(d[mi][2 * np + 1], ah[mi], bl + 2);
                    mma16816(d[mi][2 * np + 1], al[mi], bh + 2);
                }
            }
        }
        cpa_wait0();
        __syncthreads();
    }

    // Epilogue
    if (z < 2) {
#pragma unroll
        for (int mi = 0; mi < 2; mi++) {
#pragma unroll
            for (int ni = 0; ni < 8; ni++) {
                int ncol = wn * 64 + ni * 8 + tg * 2;
                int n = n0 + ncol;
                int h = n >> 6;
                int dd = n & 63;
                float b0 = sBias[ncol], b1 = sBias[ncol + 1];
#pragma unroll
                for (int rr = 0; rr < 2; rr++) {
                    int m = m0 + wm * 32 + mi * 16 + grp + rr * 8;
                    int bb = m >> 11;
                    int s  = m & 2047;
                    float vx = d[mi][ni][rr * 2 + 0] + b0;
                    float vy = d[mi][ni][rr * 2 + 1] + b1;
                    __nv_bfloat16 hx = __float2bfloat16(vx);
                    __nv_bfloat16 hy = __float2bfloat16(vy);
                    __nv_bfloat16 lx = __float2bfloat16(vx - __bfloat162float(hx));
                    __nv_bfloat16 ly = __float2bfloat16(vy - __bfloat162float(hy));
                    size_t a = ((size_t)(bb * HEADS + h) * SEQ + s) * HDIM + dd;
                    *(__nv_bfloat162*)&outh[a] = __halves2bfloat162(hx, hy);
                    *(__nv_bfloat162*)&outl[a] = __halves2bfloat162(lx, ly);
                }
            }
        }
    } else {
#pragma unroll
        for (int mi = 0; mi < 2; mi++) {
#pragma unroll
            for (int rr = 0; rr < 2; rr++) {
                int rowoff = wm * 32 + mi * 16 + grp + rr * 8;
                int i = n0 + rowoff;
                int h  = i >> 6;
                int dd = i & 63;
                float bi = sBias[rowoff];
#pragma unroll
                for (int ni = 0; ni < 8; ni++) {
                    int j = m0 + wn * 64 + ni * 8 + tg * 2;
                    int bb = j >> 11;
                    int t  = j & 2047;
                    float vx = d[mi][ni][rr * 2 + 0] + bi;
                    float vy = d[mi][ni][rr * 2 + 1] + bi;
                    __nv_bfloat16 hx = __float2bfloat16(vx);
                    __nv_bfloat16 hy = __float2bfloat16(vy);
                    __nv_bfloat16 lx = __float2bfloat16(vx - __bfloat162float(hx));
                    __nv_bfloat16 ly = __float2bfloat16(vy - __bfloat162float(hy));
                    size_t a = ((size_t)(bb * HEADS + h) * HDIM + dd) * SEQ + t;
                    *(__nv_bfloat162*)&outh[a] = __halves2bfloat162(hx, hy);
                    *(__nv_bfloat162*)&outl[a] = __halves2bfloat162(lx, ly);
                }
            }
        }
    }
}

// ---------------------------------------------------------------------------
// Flash attention (R7 — best measured). bf16 3-term, 128-thread CTAs
// (4 warps x 16 q-rows = 64 q-rows), fixed-max softmax.
// ---------------------------------------------------------------------------
#define ASTR    72
#define KTILE_B (64 * ASTR * 2)      // 9216
#define KH_OFF2 0
#define KL_OFF2 KTILE_B
#define VH_OFF2 (2 * KTILE_B)
#define VL_OFF2 (3 * KTILE_B)
#define ABUF_B  (4 * KTILE_B)        // 36864
#define ASMEM   (2 * ABUF_B)         // 73728
#define EXSC    0.18033688011112042f // 0.125 * log2(e)

__device__ __forceinline__ void attn_load(
    uint32_t bufb,
    const __nv_bfloat16* __restrict__ kh, const __nv_bfloat16* __restrict__ kl,
    const __nv_bfloat16* __restrict__ vth, const __nv_bfloat16* __restrict__ vtl,
    int t0, int tid)
{
#pragma unroll
    for (int i = 0; i < 4; i++) {
        int idx = tid + i * 128;            // 0..511
        int row = idx >> 3;                 // 0..63
        int c8  = (idx & 7) * 8;
        uint32_t so = (uint32_t)(row * ASTR + c8) * 2;
        cpa16(bufb + KH_OFF2 + so, kh  + (size_t)(t0 + row) * HDIM + c8);
        cpa16(bufb + KL_OFF2 + so, kl  + (size_t)(t0 + row) * HDIM + c8);
        cpa16(bufb + VH_OFF2 + so, vth + (size_t)row * SEQ + t0 + c8);
        cpa16(bufb + VL_OFF2 + so, vtl + (size_t)row * SEQ + t0 + c8);
    }
}

__global__ __launch_bounds__(128, 3)
void attn_mma_kernel(float* __restrict__ out)
{
    extern __shared__ char sm[];
    const uint32_t sb = smem_u32(sm);
    const int tid  = threadIdx.x;
    const int wid  = tid >> 5;
    const int lane = tid & 31;
    const int grp  = lane >> 2;
    const int tg   = lane & 3;

    const int bh = blockIdx.y;
    const int m0 = blockIdx.x * 64;

    const uint32_t lm_off = (uint32_t)(((((lane >> 4) << 3) | (lane & 7)) * 144) +
                                       ((lane >> 3) & 1) * 16);

    const __nv_bfloat16* kh  = g_kh  + (size_t)bh * SEQ * HDIM;
    const __nv_bfloat16* kl  = g_kl  + (size_t)bh * SEQ * HDIM;
    const __nv_bfloat16* vth = g_vth + (size_t)bh * HDIM * SEQ;
    const __nv_bfloat16* vtl = g_vtl + (size_t)bh * HDIM * SEQ;
    const uint32_t* Qh32 = (const uint32_t*)(g_qh + (size_t)bh * SEQ * HDIM);
    const uint32_t* Ql32 = (const uint32_t*)(g_ql + (size_t)bh * SEQ * HDIM);

    attn_load(sb, kh, kl, vth, vtl, 0, tid);
    cpa_commit();

    uint32_t ah[4][4], al[4][4];
    {
        int r0 = m0 + wid * 16 + grp;
#pragma unroll
        for (int kk = 0; kk < 4; kk++) {
            int b0 = r0 * 32 + kk * 8 + tg;
            ah[kk][0] = Qh32[b0];
            ah[kk][1] = Qh32[b0 + 8 * 32];
            ah[kk][2] = Qh32[b0 + 4];
            ah[kk][3] = Qh32[b0 + 8 * 32 + 4];
            al[kk][0] = Ql32[b0];
            al[kk][1] = Ql32[b0 + 8 * 32];
            al[kk][2] = Ql32[b0 + 4];
            al[kk][3] = Ql32[b0 + 8 * 32 + 4];
        }
    }

    float o[8][4];
    float lacc0 = 0.0f, lacc1 = 0.0f;
#pragma unroll
    for (int j = 0; j < 8; j++)
#pragma unroll
        for (int q = 0; q < 4; q++) o[j][q] = 0.0f;

    cpa_wait0();
    __syncthreads();

    for (int t0 = 0; t0 < SEQ; t0 += 64) {
        const int c = t0 >> 6;
        if (t0 + 64 < SEQ) {
            attn_load(sb + ((c + 1) & 1) * ABUF_B, kh, kl, vth, vtl, t0 + 64, tid);
            cpa_commit();
        }
        const uint32_t bufb = sb + (c & 1) * ABUF_B;
        const uint32_t khb = bufb + KH_OFF2 + lm_off;
        const uint32_t klb = bufb + KL_OFF2 + lm_off;
        const uint32_t vhb = bufb + VH_OFF2 + lm_off;
        const uint32_t vlb = bufb + VL_OFF2 + lm_off;

        float s[8][4];
#pragma unroll
        for (int j = 0; j < 8; j++)
#pragma unroll
            for (int q = 0; q < 4; q++) s[j][q] = 0.0f;

#pragma unroll
        for (int kk = 0; kk < 4; kk++) {
#pragma unroll
            for (int jp = 0; jp < 4; jp++) {
                uint32_t kbh[4], kbl[4];
                ldsm4(kbh, khb + jp * 2304 + kk * 32);
                ldsm4(kbl, klb + jp * 2304 + kk * 32);
                mma16816(s[2 * jp],     ah[kk], kbh);
                mma16816(s[2 * jp],     ah[kk], kbl);
                mma16816(s[2 * jp],     al[kk], kbh);
                mma16816(s[2 * jp + 1], ah[kk], kbh + 2);
                mma16816(s[2 * jp + 1], ah[kk], kbl + 2);
                mma16816(s[2 * jp + 1], al[kk], kbh + 2);
            }
        }

#pragma unroll
        for (int kt = 0; kt < 4; kt++) {
            const int j0 = 2 * kt, j1 = 2 * kt + 1;
            float p00 = ex2(s[j0][0] * EXSC), p01 = ex2(s[j0][1] * EXSC);
            float p02 = ex2(s[j0][2] * EXSC), p03 = ex2(s[j0][3] * EXSC);
            float p10 = ex2(s[j1][0] * EXSC), p11 = ex2(s[j1][1] * EXSC);
            float p12 = ex2(s[j1][2] * EXSC), p13 = ex2(s[j1][3] * EXSC);
            lacc0 += p00 + p01 + p10 + p11;
            lacc1 += p02 + p03 + p12 + p13;

            uint32_t pah[4], pal[4];
            pah[0] = packbf2(p00, p01);
            pah[1] = packbf2(p02, p03);
            pah[2] = packbf2(p10, p11);
            pah[3] = packbf2(p12, p13);
            __nv_bfloat162 h;
            h = *(__nv_bfloat162*)&pah[0];
            pal[0] = packbf2(p00 - __bfloat162float(h.x), p01 - __bfloat162float(h.y));
            h = *(__nv_bfloat162*)&pah[1];
            pal[1] = packbf2(p02 - __bfloat162float(h.x), p03 - __bfloat162float(h.y));
            h = *(__nv_bfloat162*)&pah[2];
            pal[2] = packbf2(p10 - __bfloat162float(h.x), p11 - __bfloat162float(h.y));
            h = *(__nv_bfloat162*)&pah[3];
            pal[3] = packbf2(p12 - __bfloat162float(h.x), p13 - __bfloat162float(h.y));

#pragma unroll
            for (int jp = 0; jp < 4; jp++) {
                uint32_t vbh[4], vbl[4];
                ldsm4(vbh, vhb + jp * 2304 + kt * 32);
                ldsm4(vbl, vlb + jp * 2304 + kt * 32);
                mma16816(o[2 * jp],     pah, vbh);
                mma16816(o[2 * jp],     pah, vbl);
                mma16816(o[2 * jp],     pal, vbh);
                mma16816(o[2 * jp + 1], pah, vbh + 2);
                mma16816(o[2 * jp + 1], pah, vbl + 2);
                mma16816(o[2 * jp + 1], pal, vbh + 2);
            }
        }

        cpa_wait0();
        __syncthreads();
    }

    lacc0 += __shfl_xor_sync(0xffffffffu, lacc0, 1);
    lacc0 += __shfl_xor_sync(0xffffffffu, lacc0, 2);
    lacc1 += __shfl_xor_sync(0xffffffffu, lacc1, 1);
    lacc1 += __shfl_xor_sync(0xffffffffu, lacc1, 2);

    const int b = bh >> 4;
    const int h = bh & 15;
    const float inv0 = 1.0f / lacc0;
    const float inv1 = 1.0f / lacc1;
    const int s0 = m0 + wid * 16 + grp;
#pragma unroll
    for (int jd = 0; jd < 8; jd++) {
        int dd = jd * 8 + tg * 2;
        float2 v0 = make_float2(o[jd][0] * inv0, o[jd][1] * inv0);
        float2 v1 = make_float2(o[jd][2] * inv1, o[jd][3] * inv1);
        *(float2*)&out[((size_t)(b * SEQ + s0)) * (HEADS * HDIM) + h * HDIM + dd] = v0;
        *(float2*)&out[((size_t)(b * SEQ + s0 + 8)) * (HEADS * HDIM) + h * HDIM + dd] = v1;
    }
}

// ---------------------------------------------------------------------------
extern "C" void kernel_launch(void* const* d_in, const int* in_sizes, int n_in,
                              void* d_out, int out_size)
{
    const float* x  = (const float*)d_in[0];
    const float* Wq = (const float*)d_in[1];
    const float* bq = (const float*)d_in[2];
    const float* Wk = (const float*)d_in[3];
    const float* bk = (const float*)d_in[4];
    const float* Wv = (const float*)d_in[5];
    const float* bv = (const float*)d_in[6];
    float* out = (float*)d_out;

    cudaFuncSetAttribute(proj_mma_kernel,
                         cudaFuncAttributeMaxDynamicSharedMemorySize, PSMEM);
    cudaFuncSetAttribute(attn_mma_kernel,
                         cudaFuncAttributeMaxDynamicSharedMemorySize, ASMEM);

    convert_all_kernel<<<8192 + 3072, 256>>>(x, Wq, Wk, Wv);
    proj_mma_kernel<<<dim3(8, 64, 3), 256, PSMEM>>>(bq, bk, bv);

    dim3 g2(SEQ / 64, NBH);
    attn_mma_kernel<<<g2, 128, ASMEM>>>(out);
}

// round 17
// speedup vs baseline: 2.0520x; 1.1967x over previous
#include <cuda_runtime.h>
#include <cuda_bf16.h>
#include <cuda_fp16.h>
#include <cstdint>
#include <math.h>

// Problem constants
#define BATCH 4
#define SEQ   2048
#define HEADS 16
#define HDIM  64
#define DIN   1024
#define M_TOT (BATCH * SEQ)   // 8192
#define NBH   (BATCH * HEADS) // 64

// Proj operands: bf16 hi/lo. Attention operands: fp16 (R13 numerics).
__device__ __nv_bfloat16 g_xh[M_TOT * DIN];
__device__ __nv_bfloat16 g_xl[M_TOT * DIN];
__device__ __nv_bfloat16 g_wh[3 * DIN * DIN];   // W transposed: [z][n][k]
__device__ __nv_bfloat16 g_wl[3 * DIN * DIN];
__device__ __half g_qh[NBH * SEQ * HDIM];   // [bh][s][d] fp16 hi
__device__ __half g_ql[NBH * SEQ * HDIM];   // [bh][s][d] fp16 lo
__device__ __half g_kh[NBH * SEQ * HDIM];   // [bh][t][d] fp16 (single)
__device__ __half g_vth[NBH * HDIM * SEQ];  // [bh][d][t] fp16 hi
__device__ __half g_vtl[NBH * HDIM * SEQ];  // [bh][d][t] fp16 lo

// ---------------------------------------------------------------------------
// Helpers
// ---------------------------------------------------------------------------
__device__ __forceinline__ uint32_t smem_u32(const void* p) {
    uint32_t a;
    asm("{ .reg .u64 t; cvta.to.shared.u64 t, %1; cvt.u32.u64 %0, t; }"
        : "=r"(a) : "l"(p));
    return a;
}
__device__ __forceinline__ void cpa16(uint32_t dst, const void* src) {
    asm volatile("cp.async.cg.shared.global [%0], [%1], 16;"
                 :: "r"(dst), "l"(src) : "memory");
}
__device__ __forceinline__ void cpa_commit() {
    asm volatile("cp.async.commit_group;" ::: "memory");
}
__device__ __forceinline__ void cpa_wait0() {
    asm volatile("cp.async.wait_group 0;" ::: "memory");
}
// bf16 mma (projection)
__device__ __forceinline__ void mma16816(float* d, const uint32_t* a,
                                         const uint32_t* b) {
    asm volatile(
        "mma.sync.aligned.m16n8k16.row.col.f32.bf16.bf16.f32 "
        "{%0,%1,%2,%3}, {%4,%5,%6,%7}, {%8,%9}, {%0,%1,%2,%3};"
        : "+f"(d[0]), "+f"(d[1]), "+f"(d[2]), "+f"(d[3])
        : "r"(a[0]), "r"(a[1]), "r"(a[2]), "r"(a[3]), "r"(b[0]), "r"(b[1]));
}
// fp16 mma (attention)
__device__ __forceinline__ void mma16816h(float* d, const uint32_t* a,
                                          const uint32_t* b) {
    asm volatile(
        "mma.sync.aligned.m16n8k16.row.col.f32.f16.f16.f32 "
        "{%0,%1,%2,%3}, {%4,%5,%6,%7}, {%8,%9}, {%0,%1,%2,%3};"
        : "+f"(d[0]), "+f"(d[1]), "+f"(d[2]), "+f"(d[3])
        : "r"(a[0]), "r"(a[1]), "r"(a[2]), "r"(a[3]), "r"(b[0]), "r"(b[1]));
}
__device__ __forceinline__ void ldsm4(uint32_t* r, uint32_t a) {
    asm volatile("ldmatrix.sync.aligned.m8n8.x4.shared.b16 {%0,%1,%2,%3}, [%4];"
                 : "=r"(r[0]), "=r"(r[1]), "=r"(r[2]), "=r"(r[3]) : "r"(a));
}
__device__ __forceinline__ uint32_t packhf2(float x, float y) {
    __half2 h = __floats2half2_rn(x, y);
    return *(uint32_t*)&h;
}
__device__ __forceinline__ float ex2(float x) {
    float y;
    asm("ex2.approx.ftz.f32 %0, %1;" : "=f"(y) : "f"(x));
    return y;
}

// ---------------------------------------------------------------------------
// Merged pre-pass (R15): fp32 -> bf16 hi/lo of x, transposed W (one launch)
// ---------------------------------------------------------------------------
__global__ __launch_bounds__(256)
void convert_all_kernel(const float* __restrict__ x,
                        const float* __restrict__ Wq,
                        const float* __restrict__ Wk,
                        const float* __restrict__ Wv)
{
    __shared__ float t[32][33];
    if (blockIdx.x < 8192) {
        int i = blockIdx.x * 256 + threadIdx.x;
        float4 v = ((const float4*)x)[i];
        __nv_bfloat16 h0 = __float2bfloat16(v.x);
        __nv_bfloat16 h1 = __float2bfloat16(v.y);
        __nv_bfloat16 h2 = __float2bfloat16(v.z);
        __nv_bfloat16 h3 = __float2bfloat16(v.w);
        __nv_bfloat16 l0 = __float2bfloat16(v.x - __bfloat162float(h0));
        __nv_bfloat16 l1 = __float2bfloat16(v.y - __bfloat162float(h1));
        __nv_bfloat16 l2 = __float2bfloat16(v.z - __bfloat162float(h2));
        __nv_bfloat16 l3 = __float2bfloat16(v.w - __bfloat162float(h3));
        __nv_bfloat162* ph = (__nv_bfloat162*)g_xh;
        __nv_bfloat162* pl = (__nv_bfloat162*)g_xl;
        ph[2 * i]     = __halves2bfloat162(h0, h1);
        ph[2 * i + 1] = __halves2bfloat162(h2, h3);
        pl[2 * i]     = __halves2bfloat162(l0, l1);
        pl[2 * i + 1] = __halves2bfloat162(l2, l3);
    } else {
        int wb  = blockIdx.x - 8192;
        int z   = wb >> 10;
        int rem = wb & 1023;
        int n0 = (rem & 31) * 32;
        int k0 = (rem >> 5) * 32;
        const float* W = (z == 0) ? Wq : ((z == 1) ? Wk : Wv);
        __nv_bfloat16* oh = g_wh + (size_t)z * DIN * DIN;
        __nv_bfloat16* ol = g_wl + (size_t)z * DIN * DIN;
        int tx = threadIdx.x & 31, ty = threadIdx.x >> 5;
#pragma unroll
        for (int r = 0; r < 4; r++)
            t[ty + r * 8][tx] = W[(size_t)(k0 + ty + r * 8) * DIN + n0 + tx];
        __syncthreads();
#pragma unroll
        for (int r = 0; r < 4; r++) {
            int n = ty + r * 8;
            float v = t[tx][n];
            __nv_bfloat16 h = __float2bfloat16(v);
            __nv_bfloat16 l = __float2bfloat16(v - __bfloat162float(h));
            oh[(size_t)(n0 + n) * DIN + k0 + tx] = h;
            ol[(size_t)(n0 + n) * DIN + k0 + tx] = l;
        }
    }
}

// ---------------------------------------------------------------------------
// Projection GEMM (R15/R7 mainloop — best measured). bf16 3-term internally;
// epilogue emits fp16: Q hi/lo, K hi only, V^T hi/lo.
// ---------------------------------------------------------------------------
#define PSTR     40
#define PTILE_B  (128 * PSTR * 2)
#define PBUF_B   (4 * PTILE_B)
#define AH_OFF   0
#define AL_OFF   PTILE_B
#define BH_OFF   (2 * PTILE_B)
#define BL_OFF   (3 * PTILE_B)
#define PSMEM    (2 * PBUF_B + 512)

__device__ __forceinline__ void proj_load_chunk(
    uint32_t bufb,
    const __nv_bfloat16* __restrict__ Ahp, const __nv_bfloat16* __restrict__ Alp,
    const __nv_bfloat16* __restrict__ Bhp, const __nv_bfloat16* __restrict__ Blp,
    int arow0, int brow0, int k0, int tid)
{
#pragma unroll
    for (int i = 0; i < 2; i++) {
        int idx = tid + i * 256;
        int row = idx >> 2;
        int c8  = (idx & 3) * 8;
        uint32_t so = (uint32_t)(row * PSTR + c8) * 2;
        cpa16(bufb + AH_OFF + so, Ahp + (size_t)(arow0 + row) * DIN + k0 + c8);
        cpa16(bufb + AL_OFF + so, Alp + (size_t)(arow0 + row) * DIN + k0 + c8);
        cpa16(bufb + BH_OFF + so, Bhp + (size_t)(brow0 + row) * DIN + k0 + c8);
        cpa16(bufb + BL_OFF + so, Blp + (size_t)(brow0 + row) * DIN + k0 + c8);
    }
}

__global__ __launch_bounds__(256, 2)
void proj_mma_kernel(const float* __restrict__ bq,
                     const float* __restrict__ bk,
                     const float* __restrict__ bv)
{
    extern __shared__ char sm[];
    const uint32_t sb = smem_u32(sm);
    const int tid = threadIdx.x;
    const int wid = tid >> 5;
    const int lane = tid & 31;
    const int grp = lane >> 2;
    const int tg  = lane & 3;
    const int wm  = wid >> 1;
    const int wn  = wid & 1;

    const int z  = blockIdx.z;
    const int n0 = blockIdx.x * 128;
    const int m0 = blockIdx.y * 128;

    const float* bias = (z == 0) ? bq : ((z == 1) ? bk : bv);
    const __nv_bfloat16* wh = g_wh + (size_t)z * DIN * DIN;
    const __nv_bfloat16* wl = g_wl + (size_t)z * DIN * DIN;
    __half* outh = (z == 0) ? g_qh : ((z == 1) ? g_kh : g_vth);
    __half* outl = (z == 0) ? g_ql : ((z == 1) ? (__half*)0 : g_vtl);

    const __nv_bfloat16 *Ahp, *Alp, *Bhp, *Blp;
    int arow0, brow0;
    if (z < 2) { Ahp = g_xh; Alp = g_xl; arow0 = m0; Bhp = wh; Blp = wl; brow0 = n0; }
    else       { Ahp = wh;   Alp = wl;   arow0 = n0; Bhp = g_xh; Blp = g_xl; brow0 = m0; }

    float* sBias = (float*)(sm + 2 * PBUF_B);
    if (tid < 128) sBias[tid] = bias[((z < 2) ? brow0 : arow0) + tid];

    const uint32_t a_off = (uint32_t)((((lane >> 3) & 1) * 8 + (lane & 7)) * 80 +
                                      (lane >> 4) * 16);
    const uint32_t b_off = (uint32_t)(((((lane >> 4) << 3) | (lane & 7)) * 80) +
                                      ((lane >> 3) & 1) * 16);

    float d[2][8][4];
#pragma unroll
    for (int mi = 0; mi < 2; mi++)
#pragma unroll
        for (int ni = 0; ni < 8; ni++)
#pragma unroll
            for (int j = 0; j < 4; j++) d[mi][ni][j] = 0.0f;

    proj_load_chunk(sb, Ahp, Alp, Bhp, Blp, arow0, brow0, 0, tid);
    cpa_commit();
    cpa_wait0();
    __syncthreads();

    const int NCHUNK = DIN / 32;
    for (int c = 0; c < NCHUNK; c++) {
        if (c + 1 < NCHUNK) {
            proj_load_chunk(sb + ((c + 1) & 1) * PBUF_B, Ahp, Alp, Bhp, Blp,
                            arow0, brow0, (c + 1) * 32, tid);
            cpa_commit();
        }
        const uint32_t bufb = sb + (c & 1) * PBUF_B;

#pragma unroll
        for (int ks = 0; ks < 2; ks++) {
            uint32_t ah[2][4], al[2][4];
#pragma unroll
            for (int mi = 0; mi < 2; mi++) {
                uint32_t ab = bufb + (uint32_t)((wm * 32 + mi * 16) * 80 + ks * 32) + a_off;
                ldsm4(ah[mi], ab + AH_OFF);
                ldsm4(al[mi], ab + AL_OFF);
            }
#pragma unroll
            for (int np = 0; np < 4; np++) {
                uint32_t bh[4], bl[4];
                uint32_t bb = bufb + (uint32_t)((wn * 64 + np * 16) * 80 + ks * 32) + b_off;
                ldsm4(bh, bb + BH_OFF);
                ldsm4(bl, bb + BL_OFF);
#pragma unroll
                for (int mi = 0; mi < 2; mi++) {
                    mma16816(d[mi][2 * np],     ah[mi], bh);
                    mma16816(d[mi][2 * np],     ah[mi], bl);
                    mma16816(d[mi][2 * np],     al[mi], bh);
                    mma16816(d[mi][2 * np + 1], ah[mi], bh + 2);
                    mma16816(d[mi][2 * np + 1], ah[mi], bl + 2);
                    mma16816(d[mi][2 * np + 1], al[mi], bh + 2);
                }
            }
        }
        cpa_wait0();
        __syncthreads();
    }

    // Epilogue -> fp16
    if (z < 2) {
#pragma unroll
        for (int mi = 0; mi < 2; mi++) {
#pragma unroll
            for (int ni = 0; ni < 8; ni++) {
                int ncol = wn * 64 + ni * 8 + tg * 2;
                int n = n0 + ncol;
                int h = n >> 6;
                int dd = n & 63;
                float b0 = sBias[ncol], b1 = sBias[ncol + 1];
#pragma unroll
                for (int rr = 0; rr < 2; rr++) {
                    int m = m0 + wm * 32 + mi * 16 + grp + rr * 8;
                    int bb = m >> 11;
                    int s  = m & 2047;
                    float vx = d[mi][ni][rr * 2 + 0] + b0;
                    float vy = d[mi][ni][rr * 2 + 1] + b1;
                    __half hx = __float2half(vx);
                    __half hy = __float2half(vy);
                    size_t a = ((size_t)(bb * HEADS + h) * SEQ + s) * HDIM + dd;
                    *(__half2*)&outh[a] = __halves2half2(hx, hy);
                    if (z == 0) {
                        __half lx = __float2half(vx - __half2float(hx));
                        __half ly = __float2half(vy - __half2float(hy));
                        *(__half2*)&outl[a] = __halves2half2(lx, ly);
                    }
                }
            }
        }
    } else {
#pragma unroll
        for (int mi = 0; mi < 2; mi++) {
#pragma unroll
            for (int rr = 0; rr < 2; rr++) {
                int rowoff = wm * 32 + mi * 16 + grp + rr * 8;
                int i = n0 + rowoff;
                int h  = i >> 6;
                int dd = i & 63;
                float bi = sBias[rowoff];
#pragma unroll
                for (int ni = 0; ni < 8; ni++) {
                    int j = m0 + wn * 64 + ni * 8 + tg * 2;
                    int bb = j >> 11;
                    int t  = j & 2047;
                    float vx = d[mi][ni][rr * 2 + 0] + bi;
                    float vy = d[mi][ni][rr * 2 + 1] + bi;
                    __half hx = __float2half(vx);
                    __half hy = __float2half(vy);
                    __half lx = __float2half(vx - __half2float(hx));
                    __half ly = __float2half(vy - __half2float(hy));
                    size_t a = ((size_t)(bb * HEADS + h) * HDIM + dd) * SEQ + t;
                    *(__half2*)&outh[a] = __halves2half2(hx, hy);
                    *(__half2*)&outl[a] = __halves2half2(lx, ly);
                }
            }
        }
    }
}

// ---------------------------------------------------------------------------
// Flash attention, fp16 2-term, FUSED per-16-key slices (no s[32] live range)
// -> regs ~112 -> occupancy 4 (16 warps/SM). 3 smem tiles/stage (Kh,Vh,Vl).
//   GEMM1: S = Qh@Kh + Ql@Kh;  GEMM2: O += P@Vh + P@Vl (P single fp16)
// ---------------------------------------------------------------------------
#define ASTR    72
#define KTILE_B (64 * ASTR * 2)      // 9216
#define KH_OFF2 0
#define VH_OFF2 KTILE_B
#define VL_OFF2 (2 * KTILE_B)
#define ABUF_B  (3 * KTILE_B)        // 27648
#define ASMEM   (2 * ABUF_B)         // 55296
#define EXSC    0.18033688011112042f // 0.125 * log2(e)

__device__ __forceinline__ void attn_load(
    uint32_t bufb,
    const __half* __restrict__ kh,
    const __half* __restrict__ vth, const __half* __restrict__ vtl,
    int t0, int tid)
{
#pragma unroll
    for (int i = 0; i < 4; i++) {
        int idx = tid + i * 128;            // 0..511
        int row = idx >> 3;                 // 0..63
        int c8  = (idx & 7) * 8;
        uint32_t so = (uint32_t)(row * ASTR + c8) * 2;
        cpa16(bufb + KH_OFF2 + so, kh  + (size_t)(t0 + row) * HDIM + c8);
        cpa16(bufb + VH_OFF2 + so, vth + (size_t)row * SEQ + t0 + c8);
        cpa16(bufb + VL_OFF2 + so, vtl + (size_t)row * SEQ + t0 + c8);
    }
}

__global__ __launch_bounds__(128, 4)
void attn_mma_kernel(float* __restrict__ out)
{
    extern __shared__ char sm[];
    const uint32_t sb = smem_u32(sm);
    const int tid  = threadIdx.x;
    const int wid  = tid >> 5;
    const int lane = tid & 31;
    const int grp  = lane >> 2;
    const int tg   = lane & 3;

    const int bh = blockIdx.y;
    const int m0 = blockIdx.x * 64;

    const uint32_t lm_off = (uint32_t)(((((lane >> 4) << 3) | (lane & 7)) * 144) +
                                       ((lane >> 3) & 1) * 16);

    const __half* kh  = g_kh  + (size_t)bh * SEQ * HDIM;
    const __half* vth = g_vth + (size_t)bh * HDIM * SEQ;
    const __half* vtl = g_vtl + (size_t)bh * HDIM * SEQ;
    const uint32_t* Qh32 = (const uint32_t*)(g_qh + (size_t)bh * SEQ * HDIM);
    const uint32_t* Ql32 = (const uint32_t*)(g_ql + (size_t)bh * SEQ * HDIM);

    attn_load(sb, kh, vth, vtl, 0, tid);
    cpa_commit();

    // Q fragments (hi + lo) resident for the whole KV loop
    uint32_t ah[4][4], al[4][4];
    {
        int r0 = m0 + wid * 16 + grp;
#pragma unroll
        for (int kk = 0; kk < 4; kk++) {
            int b0 = r0 * 32 + kk * 8 + tg;
            ah[kk][0] = Qh32[b0];
            ah[kk][1] = Qh32[b0 + 8 * 32];
            ah[kk][2] = Qh32[b0 + 4];
            ah[kk][3] = Qh32[b0 + 8 * 32 + 4];
            al[kk][0] = Ql32[b0];
            al[kk][1] = Ql32[b0 + 8 * 32];
            al[kk][2] = Ql32[b0 + 4];
            al[kk][3] = Ql32[b0 + 8 * 32 + 4];
        }
    }

    float o[8][4];
    float lacc0 = 0.0f, lacc1 = 0.0f;
#pragma unroll
    for (int j = 0; j < 8; j++)
#pragma unroll
        for (int q = 0; q < 4; q++) o[j][q] = 0.0f;

    cpa_wait0();
    __syncthreads();

    for (int t0 = 0; t0 < SEQ; t0 += 64) {
        const int c = t0 >> 6;
        if (t0 + 64 < SEQ) {
            attn_load(sb + ((c + 1) & 1) * ABUF_B, kh, vth, vtl, t0 + 64, tid);
            cpa_commit();
        }
        const uint32_t bufb = sb + (c & 1) * ABUF_B;
        const uint32_t khb = bufb + KH_OFF2 + lm_off;
        const uint32_t vhb = bufb + VH_OFF2 + lm_off;
        const uint32_t vlb = bufb + VL_OFF2 + lm_off;

        // Fully fused per 16-key slice: GEMM1 -> exp -> pack -> GEMM2.
#pragma unroll
        for (int kt = 0; kt < 4; kt++) {
            float s0[4] = {0.0f, 0.0f, 0.0f, 0.0f};
            float s1[4] = {0.0f, 0.0f, 0.0f, 0.0f};
#pragma unroll
            for (int kk = 0; kk < 4; kk++) {
                uint32_t kb[4];
                ldsm4(kb, khb + kt * 2304 + kk * 32);
                mma16816h(s0, ah[kk], kb);
                mma16816h(s0, al[kk], kb);
                mma16816h(s1, ah[kk], kb + 2);
                mma16816h(s1, al[kk], kb + 2);
            }
            float p00 = ex2(s0[0] * EXSC), p01 = ex2(s0[1] * EXSC);
            float p02 = ex2(s0[2] * EXSC), p03 = ex2(s0[3] * EXSC);
            float p10 = ex2(s1[0] * EXSC), p11 = ex2(s1[1] * EXSC);
            float p12 = ex2(s1[2] * EXSC), p13 = ex2(s1[3] * EXSC);
            lacc0 += p00 + p01 + p10 + p11;
            lacc1 += p02 + p03 + p12 + p13;

            uint32_t pah[4];
            pah[0] = packhf2(p00, p01);
            pah[1] = packhf2(p02, p03);
            pah[2] = packhf2(p10, p11);
            pah[3] = packhf2(p12, p13);

#pragma unroll
            for (int jp = 0; jp < 4; jp++) {
                uint32_t vbh[4], vbl[4];
                ldsm4(vbh, vhb + jp * 2304 + kt * 32);
                ldsm4(vbl, vlb + jp * 2304 + kt * 32);
                mma16816h(o[2 * jp],     pah, vbh);
                mma16816h(o[2 * jp],     pah, vbl);
                mma16816h(o[2 * jp + 1], pah, vbh + 2);
                mma16816h(o[2 * jp + 1], pah, vbl + 2);
            }
        }

        cpa_wait0();
        __syncthreads();
    }

    lacc0 += __shfl_xor_sync(0xffffffffu, lacc0, 1);
    lacc0 += __shfl_xor_sync(0xffffffffu, lacc0, 2);
    lacc1 += __shfl_xor_sync(0xffffffffu, lacc1, 1);
    lacc1 += __shfl_xor_sync(0xffffffffu, lacc1, 2);

    const int b = bh >> 4;
    const int h = bh & 15;
    const float inv0 = 1.0f / lacc0;
    const float inv1 = 1.0f / lacc1;
    const int s0r = m0 + wid * 16 + grp;
#pragma unroll
    for (int jd = 0; jd < 8; jd++) {
        int dd = jd * 8 + tg * 2;
        float2 v0 = make_float2(o[jd][0] * inv0, o[jd][1] * inv0);
        float2 v1 = make_float2(o[jd][2] * inv1, o[jd][3] * inv1);
        *(float2*)&out[((size_t)(b * SEQ + s0r)) * (HEADS * HDIM) + h * HDIM + dd] = v0;
        *(float2*)&out[((size_t)(b * SEQ + s0r + 8)) * (HEADS * HDIM) + h * HDIM + dd] = v1;
    }
}

// ---------------------------------------------------------------------------
extern "C" void kernel_launch(void* const* d_in, const int* in_sizes, int n_in,
                              void* d_out, int out_size)
{
    const float* x  = (const float*)d_in[0];
    const float* Wq = (const float*)d_in[1];
    const float* bq = (const float*)d_in[2];
    const float* Wk = (const float*)d_in[3];
    const float* bk = (const float*)d_in[4];
    const float* Wv = (const float*)d_in[5];
    const float* bv = (const float*)d_in[6];
    float* out = (float*)d_out;

    cudaFuncSetAttribute(proj_mma_kernel,
                         cudaFuncAttributeMaxDynamicSharedMemorySize, PSMEM);
    cudaFuncSetAttribute(attn_mma_kernel,
                         cudaFuncAttributeMaxDynamicSharedMemorySize, ASMEM);

    convert_all_kernel<<<8192 + 3072, 256>>>(x, Wq, Wk, Wv);
    proj_mma_kernel<<<dim3(8, 64, 3), 256, PSMEM>>>(bq, bk, bv);

    dim3 g2(SEQ / 64, NBH);
    attn_mma_kernel<<<g2, 128, ASMEM>>>(out);
}